// round 1
// baseline (speedup 1.0000x reference)
#include <cuda_runtime.h>
#include <cuda_bf16.h>

// ---------------------------------------------------------------------------
// ColorCNN: per-pixel MLP (64 -> 512 -> 64) + channel softmax + global
// soft-assignment reductions.
//
// K1: per 128-pixel tile: GEMM1 (tf32 mma.sync) + bias + relu + GEMM2 +
//     softmax; writes mask to global scratch (planar, fp32) and per-tile
//     partials (wc, per-k max, per-k sum).
// K2a: reduce 512 tile-partials per image into wc / chan_max / chan_mean.
// K2b: scalars mean_max, std_mean -> out[-2], out[-1].
// K3: transformed_img[b,c,p] = sum_k mask[b,k,p] * wc[b,c,k].
// ---------------------------------------------------------------------------

#define HWD   65536
#define NB    8
#define CFD   64
#define HIDD  512
#define KCD   64
#define MT    128          // pixels per K1 tile
#define NTILES 4096        // 524288 / 128
#define SA    136          // feat tile smem stride (8 mod 32 -> conflict-free frags)
#define SH    132          // h tile smem stride (4 mod 32)
#define SWS   136          // w1 chunk smem stride
#define SW2   72           // w2 chunk smem stride (8 mod 32)

// smem layout (floats)
#define AS_OFF  0
#define HS_OFF  8704                 // 64*136
#define WS_OFF  (HS_OFF + 16896)     // 128*132
#define B1_OFF  (WS_OFF + 9216)      // max(64*136, 128*72) = 9216
#define B2_OFF  (B1_OFF + 512)
#define IMG_OFF (B2_OFF + 64)
#define SMEM_FLOATS (IMG_OFF + 384)
#define SMEM_BYTES  (SMEM_FLOATS * 4)   // 143104

// global scratch (static device arrays; no runtime allocation)
__device__ float g_mask[(size_t)NB * KCD * HWD];     // 134 MB
__device__ float g_wc_part[NTILES * 192];
__device__ float g_max_part[NTILES * 64];
__device__ float g_sum_part[NTILES * 64];
__device__ float g_wc[NB * 192];                     // [b][c][k] / HW
__device__ float g_cmax[NB * KCD];
__device__ float g_cmean[NB * KCD];

__device__ __forceinline__ unsigned f2tf32(float v) {
    unsigned r;
    asm("cvt.rna.tf32.f32 %0, %1;" : "=r"(r) : "f"(v));
    return r;
}

__device__ __forceinline__ void mma8(float c[4], const unsigned a[4], const unsigned b[2]) {
    asm volatile(
        "mma.sync.aligned.m16n8k8.row.col.f32.tf32.tf32.f32 "
        "{%0,%1,%2,%3}, {%4,%5,%6,%7}, {%8,%9}, {%0,%1,%2,%3};"
        : "+f"(c[0]), "+f"(c[1]), "+f"(c[2]), "+f"(c[3])
        : "r"(a[0]), "r"(a[1]), "r"(a[2]), "r"(a[3]),
          "r"(b[0]), "r"(b[1]));
}

// ---------------------------------------------------------------------------
// K1: fused MLP + softmax + per-tile partials. 256 threads (8 warps), each
// warp owns 16 pixel-rows. 4 HID chunks of 128.
// ---------------------------------------------------------------------------
__global__ __launch_bounds__(256) void k1_mlp(
    const float* __restrict__ feat, const float* __restrict__ img,
    const float* __restrict__ w1, const float* __restrict__ b1,
    const float* __restrict__ w2, const float* __restrict__ b2)
{
    extern __shared__ float sm[];
    float* As   = sm + AS_OFF;
    float* Hs   = sm + HS_OFF;
    float* Ws   = sm + WS_OFF;
    float* B1s  = sm + B1_OFF;
    float* B2s  = sm + B2_OFF;
    float* IMGs = sm + IMG_OFF;
    float* MSK  = Hs;   // reused after GEMM2, stride 65

    const int tid  = threadIdx.x;
    const int wrp  = tid >> 5;
    const int lane = tid & 31;
    const int gid  = lane >> 2;     // groupID (row within fragment)
    const int tig  = lane & 3;      // thread-in-group (col within fragment)
    const int tile = blockIdx.x;
    const int b    = tile >> 9;               // 512 tiles per image
    const int pix0 = (tile & 511) * MT;
    const int m0   = wrp * 16;

    const float* featb = feat + (size_t)b * CFD * HWD + pix0;

    // -- stage inputs -------------------------------------------------------
    for (int e = tid; e < HIDD; e += 256) B1s[e] = b1[e];
    if (tid < KCD) B2s[tid] = b2[tid];
    for (int e = tid; e < 3 * MT; e += 256)
        IMGs[e] = img[(size_t)b * 3 * HWD + (size_t)(e >> 7) * HWD + pix0 + (e & 127)];
    for (int e = tid; e < CFD * MT; e += 256) {
        int c = e >> 7, i = e & 127;
        As[c * SA + i] = __uint_as_float(f2tf32(featb[(size_t)c * HWD + i]));
    }
    __syncthreads();

    // -- preload A fragments for GEMM1 (feat tile, K=64 -> 8 k-frags) ------
    unsigned af[8][4];
#pragma unroll
    for (int kf = 0; kf < 8; kf++) {
        int k0 = kf * 8 + tig;
        af[kf][0] = __float_as_uint(As[k0 * SA + m0 + gid]);
        af[kf][1] = __float_as_uint(As[k0 * SA + m0 + gid + 8]);
        af[kf][2] = __float_as_uint(As[(k0 + 4) * SA + m0 + gid]);
        af[kf][3] = __float_as_uint(As[(k0 + 4) * SA + m0 + gid + 8]);
    }

    // persistent logits accumulators: 8 n-tiles of 8 cols
    float lg[8][4];
#pragma unroll
    for (int t = 0; t < 8; t++) { lg[t][0] = lg[t][1] = lg[t][2] = lg[t][3] = 0.f; }

    // -- HID chunk loop ----------------------------------------------------
    for (int ch = 0; ch < 4; ch++) {
        __syncthreads();   // prev GEMM2 done reading Ws
        // load w1 chunk [64 x 128] as tf32
        for (int e = tid; e < 64 * 128; e += 256) {
            int k = e >> 7, n = e & 127;
            Ws[k * SWS + n] = __uint_as_float(f2tf32(w1[(size_t)k * HIDD + ch * 128 + n]));
        }
        __syncthreads();

        // GEMM1: h[m0..m0+15][128 cols of this chunk]
#pragma unroll 1
        for (int nt = 0; nt < 16; nt++) {
            float c4[4] = {0.f, 0.f, 0.f, 0.f};
#pragma unroll
            for (int kf = 0; kf < 8; kf++) {
                int kk = kf * 8 + tig;
                unsigned bf[2];
                bf[0] = __float_as_uint(Ws[kk * SWS + nt * 8 + gid]);
                bf[1] = __float_as_uint(Ws[(kk + 4) * SWS + nt * 8 + gid]);
                mma8(c4, af[kf], bf);
            }
            int col = nt * 8 + 2 * tig;
            int d   = ch * 128 + col;
            float bb0 = B1s[d], bb1 = B1s[d + 1];
            float v0 = fmaxf(c4[0] + bb0, 0.f), v1 = fmaxf(c4[1] + bb1, 0.f);
            float v2 = fmaxf(c4[2] + bb0, 0.f), v3 = fmaxf(c4[3] + bb1, 0.f);
            Hs[(m0 + gid)     * SH + col]     = __uint_as_float(f2tf32(v0));
            Hs[(m0 + gid)     * SH + col + 1] = __uint_as_float(f2tf32(v1));
            Hs[(m0 + gid + 8) * SH + col]     = __uint_as_float(f2tf32(v2));
            Hs[(m0 + gid + 8) * SH + col + 1] = __uint_as_float(f2tf32(v3));
        }
        __syncthreads();   // GEMM1 done reading Ws (w1), Hs written

        // load w2 chunk [128 x 64] as tf32
        for (int e = tid; e < 128 * 64; e += 256) {
            int d = e >> 6, n = e & 63;
            Ws[d * SW2 + n] = __uint_as_float(f2tf32(w2[(size_t)(ch * 128 + d) * KCD + n]));
        }
        __syncthreads();

        // GEMM2 partial: logits += h_chunk @ w2_chunk
#pragma unroll 1
        for (int kf = 0; kf < 16; kf++) {
            int k0 = kf * 8 + tig;
            unsigned a2[4];
            a2[0] = __float_as_uint(Hs[(m0 + gid)     * SH + k0]);
            a2[1] = __float_as_uint(Hs[(m0 + gid + 8) * SH + k0]);
            a2[2] = __float_as_uint(Hs[(m0 + gid)     * SH + k0 + 4]);
            a2[3] = __float_as_uint(Hs[(m0 + gid + 8) * SH + k0 + 4]);
#pragma unroll
            for (int t = 0; t < 8; t++) {
                unsigned bf[2];
                bf[0] = __float_as_uint(Ws[k0 * SW2 + t * 8 + gid]);
                bf[1] = __float_as_uint(Ws[(k0 + 4) * SW2 + t * 8 + gid]);
                mma8(lg[t], a2, bf);
            }
        }
    }
    __syncthreads();   // all mma reads of Hs complete before MSK reuse

    // -- softmax over 64 classes per pixel-row (quad = 4 consecutive lanes)
    const int r0 = m0 + gid, r1 = r0 + 8;
    float mx0 = -1e30f, mx1 = -1e30f;
#pragma unroll
    for (int t = 0; t < 8; t++) {
        int col = t * 8 + 2 * tig;
        float bb0 = B2s[col], bb1 = B2s[col + 1];
        lg[t][0] += bb0; lg[t][1] += bb1; lg[t][2] += bb0; lg[t][3] += bb1;
        mx0 = fmaxf(mx0, fmaxf(lg[t][0], lg[t][1]));
        mx1 = fmaxf(mx1, fmaxf(lg[t][2], lg[t][3]));
    }
    mx0 = fmaxf(mx0, __shfl_xor_sync(0xffffffffu, mx0, 1));
    mx0 = fmaxf(mx0, __shfl_xor_sync(0xffffffffu, mx0, 2));
    mx1 = fmaxf(mx1, __shfl_xor_sync(0xffffffffu, mx1, 1));
    mx1 = fmaxf(mx1, __shfl_xor_sync(0xffffffffu, mx1, 2));
    float s0 = 0.f, s1 = 0.f;
#pragma unroll
    for (int t = 0; t < 8; t++) {
        lg[t][0] = __expf(lg[t][0] - mx0); s0 += lg[t][0];
        lg[t][1] = __expf(lg[t][1] - mx0); s0 += lg[t][1];
        lg[t][2] = __expf(lg[t][2] - mx1); s1 += lg[t][2];
        lg[t][3] = __expf(lg[t][3] - mx1); s1 += lg[t][3];
    }
    s0 += __shfl_xor_sync(0xffffffffu, s0, 1);
    s0 += __shfl_xor_sync(0xffffffffu, s0, 2);
    s1 += __shfl_xor_sync(0xffffffffu, s1, 1);
    s1 += __shfl_xor_sync(0xffffffffu, s1, 2);
    float inv0 = 1.f / s0, inv1 = 1.f / s1;
#pragma unroll
    for (int t = 0; t < 8; t++) {
        int col = t * 8 + 2 * tig;
        MSK[r0 * 65 + col]     = lg[t][0] * inv0;
        MSK[r0 * 65 + col + 1] = lg[t][1] * inv0;
        MSK[r1 * 65 + col]     = lg[t][2] * inv1;
        MSK[r1 * 65 + col + 1] = lg[t][3] * inv1;
    }
    __syncthreads();

    // -- (a) store mask planar to global scratch ---------------------------
    size_t mbase = (size_t)b * KCD * HWD + pix0;
    for (int e = tid; e < KCD * MT; e += 256) {
        int k = e >> 7, i = e & 127;
        g_mask[mbase + (size_t)k * HWD + i] = MSK[i * 65 + k];
    }
    // -- (b) wc partials (threads 0..191), (c) per-k max/sum (192..255) ---
    if (tid < 192) {
        int c = tid >> 6, k = tid & 63;
        float s = 0.f;
        for (int i = 0; i < MT; i++) s += IMGs[c * MT + i] * MSK[i * 65 + k];
        g_wc_part[tile * 192 + tid] = s;
    } else {
        int k = tid - 192;
        float mx = -1e30f, smv = 0.f;
        for (int i = 0; i < MT; i++) {
            float v = MSK[i * 65 + k];
            mx = fmaxf(mx, v); smv += v;
        }
        g_max_part[tile * 64 + k] = mx;
        g_sum_part[tile * 64 + k] = smv;
    }
}

// ---------------------------------------------------------------------------
// K2a: one warp per reduction job (512 tile-partials each).
// jobs: [0,1536) wc, [1536,2048) chan_max, [2048,2560) chan_mean
// ---------------------------------------------------------------------------
__global__ __launch_bounds__(256) void k2a_reduce() {
    int job  = blockIdx.x * 8 + (threadIdx.x >> 5);
    int lane = threadIdx.x & 31;
    if (job < 1536) {
        int b = job / 192, r = job % 192;
        const float* p = g_wc_part + (size_t)b * 512 * 192 + r;
        float s = 0.f;
        for (int i = lane; i < 512; i += 32) s += p[(size_t)i * 192];
        for (int o = 16; o; o >>= 1) s += __shfl_xor_sync(0xffffffffu, s, o);
        if (lane == 0) g_wc[job] = s * (1.f / HWD);
    } else if (job < 2048) {
        int j = job - 1536; int b = j >> 6, k = j & 63;
        const float* p = g_max_part + (size_t)b * 512 * 64 + k;
        float m = -1e30f;
        for (int i = lane; i < 512; i += 32) m = fmaxf(m, p[(size_t)i * 64]);
        for (int o = 16; o; o >>= 1) m = fmaxf(m, __shfl_xor_sync(0xffffffffu, m, o));
        if (lane == 0) g_cmax[j] = m;
    } else if (job < 2560) {
        int j = job - 2048; int b = j >> 6, k = j & 63;
        const float* p = g_sum_part + (size_t)b * 512 * 64 + k;
        float s = 0.f;
        for (int i = lane; i < 512; i += 32) s += p[(size_t)i * 64];
        for (int o = 16; o; o >>= 1) s += __shfl_xor_sync(0xffffffffu, s, o);
        if (lane == 0) g_cmean[j] = s * (1.f / HWD);
    }
}

// ---------------------------------------------------------------------------
// K2b: scalars. 1 CTA x 512 threads.
// ---------------------------------------------------------------------------
__global__ __launch_bounds__(512) void k2b_scalars(float* __restrict__ out, int out_size) {
    __shared__ float red[512];
    __shared__ float cmn[512];
    __shared__ float stds[8];
    int t = threadIdx.x;
    red[t] = g_cmax[t];
    cmn[t] = g_cmean[t];
    __syncthreads();
    for (int s = 256; s > 0; s >>= 1) {
        if (t < s) red[t] += red[t + s];
        __syncthreads();
    }
    if (t < 8) {
        float m = 0.f;
        for (int k = 0; k < 64; k++) m += cmn[t * 64 + k];
        m *= (1.f / 64.f);
        float v = 0.f;
        for (int k = 0; k < 64; k++) { float d = cmn[t * 64 + k] - m; v += d * d; }
        stds[t] = sqrtf(v * (1.f / 63.f));
    }
    __syncthreads();
    if (t == 0) {
        float s = 0.f;
        for (int b = 0; b < 8; b++) s += stds[b];
        out[out_size - 2] = red[0] * (1.f / 512.f);  // mean_max
        out[out_size - 1] = s * (1.f / 8.f);         // std_mean
    }
}

// ---------------------------------------------------------------------------
// K3: transformed_img[b,c,p] = sum_k mask[b,k,p] * wc[b,c,k]
// ---------------------------------------------------------------------------
__global__ __launch_bounds__(256) void k3_expand(float* __restrict__ out) {
    int p  = blockIdx.x * 256 + threadIdx.x;   // global pixel
    int b  = p >> 16;
    int pl = p & (HWD - 1);
    __shared__ float wcs[192];
    if (threadIdx.x < 192) wcs[threadIdx.x] = g_wc[b * 192 + threadIdx.x];
    __syncthreads();
    const float* mp = g_mask + (size_t)b * KCD * HWD + pl;
    float a0 = 0.f, a1 = 0.f, a2 = 0.f;
#pragma unroll 8
    for (int k = 0; k < KCD; k++) {
        float m = mp[(size_t)k * HWD];
        a0 += m * wcs[k];
        a1 += m * wcs[64 + k];
        a2 += m * wcs[128 + k];
    }
    out[((size_t)b * 3 + 0) * HWD + pl] = a0;
    out[((size_t)b * 3 + 1) * HWD + pl] = a1;
    out[((size_t)b * 3 + 2) * HWD + pl] = a2;
}

// ---------------------------------------------------------------------------
extern "C" void kernel_launch(void* const* d_in, const int* in_sizes, int n_in,
                              void* d_out, int out_size) {
    const float* img  = (const float*)d_in[0];
    const float* feat = (const float*)d_in[1];
    // d_in[2] = coord_map (unused by reference)
    const float* w1 = (const float*)d_in[3];
    const float* b1 = (const float*)d_in[4];
    const float* w2 = (const float*)d_in[5];
    const float* b2 = (const float*)d_in[6];
    float* out = (float*)d_out;

    cudaFuncSetAttribute(k1_mlp, cudaFuncAttributeMaxDynamicSharedMemorySize, SMEM_BYTES);

    k1_mlp<<<NTILES, 256, SMEM_BYTES>>>(feat, img, w1, b1, w2, b2);
    k2a_reduce<<<320, 256>>>();
    k2b_scalars<<<1, 512>>>(out, out_size);
    k3_expand<<<2048, 256>>>(out);
}

// round 5
// speedup vs baseline: 2.2427x; 2.2427x over previous
#include <cuda_runtime.h>
#include <cuda_bf16.h>

// ---------------------------------------------------------------------------
// ColorCNN round 5 (second resubmit of the round-3 kernel; two infra flakes).
//   k0_prep: w1/w2 -> rna-rounded tf32 (stored as f32) in device scratch.
//   k1_mlp:  GEMM1 (tf32 mma) -> bias+relu -> shfl permute -> GEMM2 -> softmax
//            -> mask scratch + per-tile partials. Register-resident H.
//   k2a/k2b: reductions + scalars. k3: mask @ wc re-expansion (float4).
// ---------------------------------------------------------------------------

#define HWD   65536
#define NB    8
#define CFD   64
#define HIDD  512
#define KCD   64
#define MT    128
#define NTILES 4096

#define SW1   136   // w1 chunk stride (8 mod 32 -> conflict-free B frags)
#define SW2   72    // w2 chunk stride (8 mod 32)
#define SAO   136   // feat tile stride

// smem float offsets
#define W2S_OFF 0                    // 128*72 = 9216 (also feat tile, then mask)
#define W1S_OFF 9216                 // 64*136 = 8704
#define B1_OFF  17920                // 512
#define B2_OFF  18432                // 64
#define IMG_OFF 18496                // 384
#define SMEM_FLOATS 18880
#define SMEM_BYTES  (SMEM_FLOATS * 4)   // 75520

// global scratch
__device__ float g_mask[(size_t)NB * KCD * HWD];
__device__ float g_w1c[CFD * HIDD];        // rna-rounded w1
__device__ float g_w2c[HIDD * KCD];        // rna-rounded w2
__device__ float g_wc_part[NTILES * 192];
__device__ float g_max_part[NTILES * 64];
__device__ float g_sum_part[NTILES * 64];
__device__ float g_wc[NB * 192];
__device__ float g_cmax[NB * KCD];
__device__ float g_cmean[NB * KCD];

__device__ __forceinline__ unsigned f2tf32(float v) {
    unsigned r;
    asm("cvt.rna.tf32.f32 %0, %1;" : "=r"(r) : "f"(v));
    return r;
}

__device__ __forceinline__ void mma8(float c[4], const unsigned a[4], const unsigned b[2]) {
    asm volatile(
        "mma.sync.aligned.m16n8k8.row.col.f32.tf32.tf32.f32 "
        "{%0,%1,%2,%3}, {%4,%5,%6,%7}, {%8,%9}, {%0,%1,%2,%3};"
        : "+f"(c[0]), "+f"(c[1]), "+f"(c[2]), "+f"(c[3])
        : "r"(a[0]), "r"(a[1]), "r"(a[2]), "r"(a[3]),
          "r"(b[0]), "r"(b[1]));
}

__device__ __forceinline__ void cpa16(unsigned dst, const void* src) {
    asm volatile("cp.async.cg.shared.global [%0], [%1], 16;" :: "r"(dst), "l"(src));
}
#define CP_COMMIT() asm volatile("cp.async.commit_group;")
#define CP_WAIT0()  asm volatile("cp.async.wait_group 0;")

// ---------------------------------------------------------------------------
// k0_prep: round weights to tf32 (rna) once; K1 then loads pre-rounded values.
// ---------------------------------------------------------------------------
__global__ __launch_bounds__(256) void k0_prep(
    const float* __restrict__ w1, const float* __restrict__ w2)
{
    int i = blockIdx.x * 256 + threadIdx.x;
    if (i < CFD * HIDD)
        g_w1c[i] = __uint_as_float(f2tf32(w1[i]));
    int j = i - CFD * HIDD;
    if (j >= 0 && j < HIDD * KCD)
        g_w2c[j] = __uint_as_float(f2tf32(w2[j]));
}

// ---------------------------------------------------------------------------
__global__ __launch_bounds__(256, 2) void k1_mlp(
    const float* __restrict__ feat, const float* __restrict__ img,
    const float* __restrict__ b1, const float* __restrict__ b2)
{
    extern __shared__ float sm[];
    unsigned smb;
    asm("{ .reg .u64 t; cvta.to.shared.u64 t, %1; cvt.u32.u64 %0, t; }"
        : "=r"(smb) : "l"(sm));

    const int tid  = threadIdx.x;
    const int lane = tid & 31;
    const int wrp  = tid >> 5;
    const int gid  = lane >> 2;
    const int tig  = lane & 3;
    const int tile = blockIdx.x;
    const int b    = tile >> 9;
    const int pix0 = (tile & 511) * MT;
    const int m0   = wrp * 16;

    const float* featb = feat + (size_t)b * CFD * HWD + pix0;

    // ---- stage feat tile (into W2S region) + w1 chunk 0 via cp.async ----
    for (int it = tid; it < 2048; it += 256) {          // feat: 64 rows x 128
        int r = it >> 5, c16 = (it & 31) << 2;
        cpa16(smb + (unsigned)(W2S_OFF + r * SAO + c16) * 4u,
              featb + (size_t)r * HWD + c16);
    }
    for (int it = tid; it < 2048; it += 256) {          // w1 chunk 0: 64 x 128
        int r = it >> 5, c16 = (it & 31) << 2;
        cpa16(smb + (unsigned)(W1S_OFF + r * SW1 + c16) * 4u,
              g_w1c + (size_t)r * HIDD + c16);
    }
    CP_COMMIT();
    // biases + img via plain stores
    for (int e = tid; e < HIDD; e += 256) sm[B1_OFF + e] = b1[e];
    if (tid < KCD) sm[B2_OFF + tid] = b2[tid];
    for (int e = tid; e < 3 * MT; e += 256)
        sm[IMG_OFF + e] = img[(size_t)b * 3 * HWD + (size_t)(e >> 7) * HWD + pix0 + (e & 127)];
    CP_WAIT0();
    __syncthreads();

    // ---- preload GEMM1 A fragments (feat tile, cvt.rna) ----
    unsigned af[8][4];
#pragma unroll
    for (int kf = 0; kf < 8; kf++) {
        int k0 = kf * 8 + tig;
        af[kf][0] = f2tf32(sm[W2S_OFF + k0 * SAO + m0 + gid]);
        af[kf][1] = f2tf32(sm[W2S_OFF + k0 * SAO + m0 + gid + 8]);
        af[kf][2] = f2tf32(sm[W2S_OFF + (k0 + 4) * SAO + m0 + gid]);
        af[kf][3] = f2tf32(sm[W2S_OFF + (k0 + 4) * SAO + m0 + gid + 8]);
    }
    __syncthreads();   // feat tile dead; W2S region can be overwritten

    // ---- w2 chunk 0 ----
    for (int it = tid; it < 2048; it += 256) {          // 128 rows x 64
        int r = it >> 4, c16 = (it & 15) << 2;
        cpa16(smb + (unsigned)(W2S_OFF + r * SW2 + c16) * 4u,
              g_w2c + (size_t)r * KCD + c16);
    }
    CP_COMMIT();
    CP_WAIT0();
    __syncthreads();

    float lg[8][4];
#pragma unroll
    for (int t = 0; t < 8; t++) { lg[t][0] = lg[t][1] = lg[t][2] = lg[t][3] = 0.f; }

    // ---- HID chunk loop ----
    for (int ch = 0; ch < 4; ch++) {
        if (ch > 0) {
            __syncthreads();   // prev chunk's reads of both bufs done
            for (int it = tid; it < 2048; it += 256) {
                int r = it >> 5, c16 = (it & 31) << 2;
                cpa16(smb + (unsigned)(W1S_OFF + r * SW1 + c16) * 4u,
                      g_w1c + (size_t)r * HIDD + ch * 128 + c16);
            }
            for (int it = tid; it < 2048; it += 256) {
                int r = it >> 4, c16 = (it & 15) << 2;
                cpa16(smb + (unsigned)(W2S_OFF + r * SW2 + c16) * 4u,
                      g_w2c + (size_t)(ch * 128 + r) * KCD + c16);
            }
            CP_COMMIT();
            CP_WAIT0();
            __syncthreads();
        }

#pragma unroll 1
        for (int nt = 0; nt < 16; nt++) {
            const int nc = nt * 8 + gid;
            float cA[4] = {0.f, 0.f, 0.f, 0.f};
            float cB[4] = {0.f, 0.f, 0.f, 0.f};
#pragma unroll
            for (int kf = 0; kf < 8; kf += 2) {
                unsigned bf[2];
                int k0 = kf * 8 + tig;
                bf[0] = __float_as_uint(sm[W1S_OFF + k0 * SW1 + nc]);
                bf[1] = __float_as_uint(sm[W1S_OFF + (k0 + 4) * SW1 + nc]);
                mma8(cA, af[kf], bf);
                int k1 = k0 + 8;
                bf[0] = __float_as_uint(sm[W1S_OFF + k1 * SW1 + nc]);
                bf[1] = __float_as_uint(sm[W1S_OFF + (k1 + 4) * SW1 + nc]);
                mma8(cB, af[kf + 1], bf);
            }
            // bias + relu + tf32 cvt
            int d0 = ch * 128 + nt * 8 + 2 * tig;
            float bb0 = sm[B1_OFF + d0], bb1 = sm[B1_OFF + d0 + 1];
            unsigned u0 = f2tf32(fmaxf(cA[0] + cB[0] + bb0, 0.f));
            unsigned u1 = f2tf32(fmaxf(cA[1] + cB[1] + bb1, 0.f));
            unsigned u2 = f2tf32(fmaxf(cA[2] + cB[2] + bb0, 0.f));
            unsigned u3 = f2tf32(fmaxf(cA[3] + cB[3] + bb1, 0.f));
            // permute GEMM1 C-frag -> GEMM2 A-frag via shuffles
            int base = lane & ~3;
            int s0l = base + (tig >> 1);
            int s1l = s0l + 2;
            unsigned a2[4];
            unsigned xa, xb;
            xa = __shfl_sync(0xffffffffu, u0, s0l);
            xb = __shfl_sync(0xffffffffu, u1, s0l);
            a2[0] = (tig & 1) ? xb : xa;              // H[gid][tig]
            xa = __shfl_sync(0xffffffffu, u2, s0l);
            xb = __shfl_sync(0xffffffffu, u3, s0l);
            a2[1] = (tig & 1) ? xb : xa;              // H[gid+8][tig]
            xa = __shfl_sync(0xffffffffu, u0, s1l);
            xb = __shfl_sync(0xffffffffu, u1, s1l);
            a2[2] = (tig & 1) ? xb : xa;              // H[gid][tig+4]
            xa = __shfl_sync(0xffffffffu, u2, s1l);
            xb = __shfl_sync(0xffffffffu, u3, s1l);
            a2[3] = (tig & 1) ? xb : xa;              // H[gid+8][tig+4]
            // GEMM2: logits += Hblk @ w2[rows nt*8..nt*8+8]
            int kr = nt * 8 + tig;
#pragma unroll
            for (int t = 0; t < 8; t++) {
                unsigned bf[2];
                bf[0] = __float_as_uint(sm[W2S_OFF + kr * SW2 + t * 8 + gid]);
                bf[1] = __float_as_uint(sm[W2S_OFF + (kr + 4) * SW2 + t * 8 + gid]);
                mma8(lg[t], a2, bf);
            }
        }
    }
    __syncthreads();   // all reads of weight bufs done; W2S region -> mask

    // ---- softmax over 64 classes (quad-level reductions) ----
    float* MSK = sm + W2S_OFF;   // stride 65
    const int r0 = m0 + gid, r1 = r0 + 8;
    float mx0 = -1e30f, mx1 = -1e30f;
#pragma unroll
    for (int t = 0; t < 8; t++) {
        int col = t * 8 + 2 * tig;
        float bb0 = sm[B2_OFF + col], bb1 = sm[B2_OFF + col + 1];
        lg[t][0] += bb0; lg[t][1] += bb1; lg[t][2] += bb0; lg[t][3] += bb1;
        mx0 = fmaxf(mx0, fmaxf(lg[t][0], lg[t][1]));
        mx1 = fmaxf(mx1, fmaxf(lg[t][2], lg[t][3]));
    }
    mx0 = fmaxf(mx0, __shfl_xor_sync(0xffffffffu, mx0, 1));
    mx0 = fmaxf(mx0, __shfl_xor_sync(0xffffffffu, mx0, 2));
    mx1 = fmaxf(mx1, __shfl_xor_sync(0xffffffffu, mx1, 1));
    mx1 = fmaxf(mx1, __shfl_xor_sync(0xffffffffu, mx1, 2));
    float s0 = 0.f, s1 = 0.f;
#pragma unroll
    for (int t = 0; t < 8; t++) {
        lg[t][0] = __expf(lg[t][0] - mx0); s0 += lg[t][0];
        lg[t][1] = __expf(lg[t][1] - mx0); s0 += lg[t][1];
        lg[t][2] = __expf(lg[t][2] - mx1); s1 += lg[t][2];
        lg[t][3] = __expf(lg[t][3] - mx1); s1 += lg[t][3];
    }
    s0 += __shfl_xor_sync(0xffffffffu, s0, 1);
    s0 += __shfl_xor_sync(0xffffffffu, s0, 2);
    s1 += __shfl_xor_sync(0xffffffffu, s1, 1);
    s1 += __shfl_xor_sync(0xffffffffu, s1, 2);
    float inv0 = 1.f / s0, inv1 = 1.f / s1;
#pragma unroll
    for (int t = 0; t < 8; t++) {
        int col = t * 8 + 2 * tig;
        MSK[r0 * 65 + col]     = lg[t][0] * inv0;
        MSK[r0 * 65 + col + 1] = lg[t][1] * inv0;
        MSK[r1 * 65 + col]     = lg[t][2] * inv1;
        MSK[r1 * 65 + col + 1] = lg[t][3] * inv1;
    }
    __syncthreads();

    // ---- mask -> global (planar), per-tile partials ----
    size_t mbase = (size_t)b * KCD * HWD + pix0;
    for (int e = tid; e < KCD * MT; e += 256) {
        int k = e >> 7, i = e & 127;
        g_mask[mbase + (size_t)k * HWD + i] = MSK[i * 65 + k];
    }
    if (tid < 192) {
        int c = tid >> 6, k = tid & 63;
        float s = 0.f;
        for (int i = 0; i < MT; i++) s += sm[IMG_OFF + c * MT + i] * MSK[i * 65 + k];
        g_wc_part[tile * 192 + tid] = s;
    } else {
        int k = tid - 192;
        float mx = -1e30f, smv = 0.f;
        for (int i = 0; i < MT; i++) {
            float v = MSK[i * 65 + k];
            mx = fmaxf(mx, v); smv += v;
        }
        g_max_part[tile * 64 + k] = mx;
        g_sum_part[tile * 64 + k] = smv;
    }
}

// ---------------------------------------------------------------------------
__global__ __launch_bounds__(256) void k2a_reduce() {
    int job  = blockIdx.x * 8 + (threadIdx.x >> 5);
    int lane = threadIdx.x & 31;
    if (job < 1536) {
        int b = job / 192, r = job % 192;
        const float* p = g_wc_part + (size_t)b * 512 * 192 + r;
        float s = 0.f;
        for (int i = lane; i < 512; i += 32) s += p[(size_t)i * 192];
        for (int o = 16; o; o >>= 1) s += __shfl_xor_sync(0xffffffffu, s, o);
        if (lane == 0) g_wc[job] = s * (1.f / HWD);
    } else if (job < 2048) {
        int j = job - 1536; int b = j >> 6, k = j & 63;
        const float* p = g_max_part + (size_t)b * 512 * 64 + k;
        float m = -1e30f;
        for (int i = lane; i < 512; i += 32) m = fmaxf(m, p[(size_t)i * 64]);
        for (int o = 16; o; o >>= 1) m = fmaxf(m, __shfl_xor_sync(0xffffffffu, m, o));
        if (lane == 0) g_cmax[j] = m;
    } else if (job < 2560) {
        int j = job - 2048; int b = j >> 6, k = j & 63;
        const float* p = g_sum_part + (size_t)b * 512 * 64 + k;
        float s = 0.f;
        for (int i = lane; i < 512; i += 32) s += p[(size_t)i * 64];
        for (int o = 16; o; o >>= 1) s += __shfl_xor_sync(0xffffffffu, s, o);
        if (lane == 0) g_cmean[j] = s * (1.f / HWD);
    }
}

// ---------------------------------------------------------------------------
__global__ __launch_bounds__(512) void k2b_scalars(float* __restrict__ out, int out_size) {
    __shared__ float red[512];
    __shared__ float cmn[512];
    __shared__ float stds[8];
    int t = threadIdx.x;
    red[t] = g_cmax[t];
    cmn[t] = g_cmean[t];
    __syncthreads();
    for (int s = 256; s > 0; s >>= 1) {
        if (t < s) red[t] += red[t + s];
        __syncthreads();
    }
    if (t < 8) {
        float m = 0.f;
        for (int k = 0; k < 64; k++) m += cmn[t * 64 + k];
        m *= (1.f / 64.f);
        float v = 0.f;
        for (int k = 0; k < 64; k++) { float d = cmn[t * 64 + k] - m; v += d * d; }
        stds[t] = sqrtf(v * (1.f / 63.f));
    }
    __syncthreads();
    if (t == 0) {
        float s = 0.f;
        for (int b = 0; b < 8; b++) s += stds[b];
        out[out_size - 2] = red[0] * (1.f / 512.f);
        out[out_size - 1] = s * (1.f / 8.f);
    }
}

// ---------------------------------------------------------------------------
// K3: transformed_img, float4-vectorized (4 pixels/thread).
// ---------------------------------------------------------------------------
__global__ __launch_bounds__(256) void k3_expand(float* __restrict__ out) {
    int q  = blockIdx.x * 256 + threadIdx.x;   // quad index (4 pixels)
    int b  = q >> 14;                          // 16384 quads per image
    int pl = (q & 16383) << 2;
    __shared__ float wcs[192];
    if (threadIdx.x < 192) wcs[threadIdx.x] = g_wc[b * 192 + threadIdx.x];
    __syncthreads();
    const float* mp = g_mask + (size_t)b * KCD * HWD + pl;
    float4 a0 = {0.f, 0.f, 0.f, 0.f};
    float4 a1 = {0.f, 0.f, 0.f, 0.f};
    float4 a2 = {0.f, 0.f, 0.f, 0.f};
#pragma unroll 8
    for (int k = 0; k < KCD; k++) {
        float4 m = *(const float4*)(mp + (size_t)k * HWD);
        float w0 = wcs[k], w1v = wcs[64 + k], w2v = wcs[128 + k];
        a0.x += m.x * w0;  a0.y += m.y * w0;  a0.z += m.z * w0;  a0.w += m.w * w0;
        a1.x += m.x * w1v; a1.y += m.y * w1v; a1.z += m.z * w1v; a1.w += m.w * w1v;
        a2.x += m.x * w2v; a2.y += m.y * w2v; a2.z += m.z * w2v; a2.w += m.w * w2v;
    }
    *(float4*)(out + ((size_t)b * 3 + 0) * HWD + pl) = a0;
    *(float4*)(out + ((size_t)b * 3 + 1) * HWD + pl) = a1;
    *(float4*)(out + ((size_t)b * 3 + 2) * HWD + pl) = a2;
}

// ---------------------------------------------------------------------------
extern "C" void kernel_launch(void* const* d_in, const int* in_sizes, int n_in,
                              void* d_out, int out_size) {
    const float* img  = (const float*)d_in[0];
    const float* feat = (const float*)d_in[1];
    const float* w1 = (const float*)d_in[3];
    const float* b1 = (const float*)d_in[4];
    const float* w2 = (const float*)d_in[5];
    const float* b2 = (const float*)d_in[6];
    float* out = (float*)d_out;

    cudaFuncSetAttribute(k1_mlp, cudaFuncAttributeMaxDynamicSharedMemorySize, SMEM_BYTES);

    k0_prep<<<256, 256>>>(w1, w2);
    k1_mlp<<<NTILES, 256, SMEM_BYTES>>>(feat, img, b1, b2);
    k2a_reduce<<<320, 256>>>();
    k2b_scalars<<<1, 512>>>(out, out_size);
    k3_expand<<<512, 256>>>(out);
}